// round 1
// baseline (speedup 1.0000x reference)
#include <cuda_runtime.h>
#include <cstdint>

// ToPatches: x[16,23,120200] -> patches[16,23,1000,200] (+ mask[16,23,1000])
// patches[b,c,p,i] = x[b,c, p*150+i] for p<801 else 0 ; mask = (p<801)
// Output layout assumed: flat concat [patches..., mask...]

namespace {
constexpr int B = 16;
constexpr int C = 23;
constexpr int T = 120200;
constexpr int P = 1000;        // MAX_PATCHES
constexpr int PS = 200;        // PATCH_SIZE
constexpr int STRIDE = 150;
constexpr int ACTUAL = (T - PS) / STRIDE + 1;   // 801
constexpr int PS4 = PS / 4;                     // 50 float4 per patch
constexpr int PER_BC4 = P * PS4;                // 50000 float4 per (b,c)
constexpr long long PATCH_ELEMS = (long long)B * C * P * PS;  // 73,600,000
constexpr long long N4 = PATCH_ELEMS / 4;                     // 18,400,000
constexpr int MASK_N = B * C * P;                             // 368,000
}

__global__ __launch_bounds__(256) void topatches_kernel(
    const float* __restrict__ x, float4* __restrict__ out)
{
    long long idx4 = (long long)blockIdx.x * blockDim.x + threadIdx.x;
    if (idx4 >= N4) return;

    int bc = (int)(idx4 / PER_BC4);
    int r  = (int)(idx4 - (long long)bc * PER_BC4);
    int p  = r / PS4;
    int i4 = r - p * PS4;

    float4 v;
    if (p < ACTUAL) {
        // element offset = bc*T + p*STRIDE + 4*i4 — always even -> float2 aligned
        const float2* src = reinterpret_cast<const float2*>(
            x + (long long)bc * T + p * STRIDE + (i4 << 2));
        float2 a = src[0];
        float2 b = src[1];
        v = make_float4(a.x, a.y, b.x, b.y);
    } else {
        v = make_float4(0.f, 0.f, 0.f, 0.f);
    }
    out[idx4] = v;
}

__global__ __launch_bounds__(256) void mask_kernel(float* __restrict__ mask)
{
    int idx = blockIdx.x * blockDim.x + threadIdx.x;
    if (idx >= MASK_N) return;
    int p = idx % P;
    mask[idx] = (p < ACTUAL) ? 1.0f : 0.0f;
}

extern "C" void kernel_launch(void* const* d_in, const int* in_sizes, int n_in,
                              void* d_out, int out_size)
{
    const float* x = (const float*)d_in[0];
    float* out = (float*)d_out;

    {
        int threads = 256;
        long long blocks = (N4 + threads - 1) / threads;
        topatches_kernel<<<(unsigned)blocks, threads>>>(x, (float4*)out);
    }
    // Mask appended after the patch block (if present in out_size)
    if ((long long)out_size >= PATCH_ELEMS + MASK_N) {
        int threads = 256;
        int blocks = (MASK_N + threads - 1) / threads;
        mask_kernel<<<blocks, threads>>>(out + PATCH_ELEMS);
    }
}

// round 2
// speedup vs baseline: 1.0027x; 1.0027x over previous
#include <cuda_runtime.h>
#include <cstdint>

// ToPatches: x[16,23,120200] -> patches[16,23,1000,200] (+ mask[16,23,1000])
// patches[b,c,p,i] = x[b,c, p*150+i] for p<801 else 0 ; mask = (p<801)
// Output layout: flat concat [patches..., mask...]
// Fused single kernel: grid covers patch float4s then mask float4s.

namespace {
constexpr int B = 16;
constexpr int C = 23;
constexpr int T = 120200;
constexpr int P = 1000;        // MAX_PATCHES
constexpr int PS = 200;        // PATCH_SIZE
constexpr int STRIDE = 150;
constexpr int ACTUAL = (T - PS) / STRIDE + 1;   // 801
constexpr int PS4 = PS / 4;                     // 50 float4 per patch
constexpr int PER_BC4 = P * PS4;                // 50000 float4 per (b,c)
constexpr long long PATCH_ELEMS = (long long)B * C * P * PS;  // 73,600,000
constexpr long long N4 = PATCH_ELEMS / 4;                     // 18,400,000
constexpr int MASK_N = B * C * P;                             // 368,000
constexpr int MASK_N4 = MASK_N / 4;                           // 92,000
constexpr long long TOTAL4 = N4 + MASK_N4;
}

__global__ __launch_bounds__(256) void topatches_fused_kernel(
    const float* __restrict__ x, float4* __restrict__ out)
{
    long long idx4 = (long long)blockIdx.x * blockDim.x + threadIdx.x;
    if (idx4 >= TOTAL4) return;

    if (idx4 < N4) {
        int bc = (int)(idx4 / PER_BC4);
        int r  = (int)(idx4 - (long long)bc * PER_BC4);
        int p  = r / PS4;
        int i4 = r - p * PS4;

        float4 v;
        if (p < ACTUAL) {
            // element offset = bc*T + p*STRIDE + 4*i4 — always even -> float2 aligned
            const float2* src = reinterpret_cast<const float2*>(
                x + (long long)bc * T + p * STRIDE + (i4 << 2));
            float2 a = src[0];
            float2 b = src[1];
            v = make_float4(a.x, a.y, b.x, b.y);
        } else {
            v = make_float4(0.f, 0.f, 0.f, 0.f);
        }
        // Output is write-once, never re-read: streaming (evict-first) store
        __stcs(&out[idx4], v);
    } else {
        // Mask tail: 4 consecutive mask elements per thread.
        // P=1000 is divisible by 4, so all 4 share bc; p = m%P .. m%P+3.
        int m4 = (int)(idx4 - N4);          // 0 .. MASK_N4-1
        int m  = m4 << 2;                   // first element index
        int p  = m % P;                     // first p
        float4 v = make_float4(
            (p + 0 < ACTUAL) ? 1.0f : 0.0f,
            (p + 1 < ACTUAL) ? 1.0f : 0.0f,
            (p + 2 < ACTUAL) ? 1.0f : 0.0f,
            (p + 3 < ACTUAL) ? 1.0f : 0.0f);
        __stcs(&out[idx4], v);              // contiguous: N4 + m4 in float4 space
    }
}

extern "C" void kernel_launch(void* const* d_in, const int* in_sizes, int n_in,
                              void* d_out, int out_size)
{
    const float* x = (const float*)d_in[0];
    float4* out = (float4*)d_out;

    int threads = 256;
    long long blocks = (TOTAL4 + threads - 1) / threads;
    topatches_fused_kernel<<<(unsigned)blocks, threads>>>(x, out);
}